// round 6
// baseline (speedup 1.0000x reference)
#include <cuda_runtime.h>
#include <math.h>

#define SQ   512
#define BB   64
#define FIN  512
#define HH   512
#define G4   2048   // 4*H

typedef unsigned long long ull;

// Scratch (static device arrays: allocation-guard safe)
__device__ float g_xg[(long long)SQ * BB * G4];   // input-projection gates [S, B, 4H]
__device__ float g_c [(long long)SQ * BB * HH];   // fallback c-state history
__device__ int   g_bar[SQ];                       // per-step h-ready counters

__device__ __forceinline__ float sig(float x) { return 1.0f / (1.0f + expf(-x)); }

__device__ __forceinline__ void ffma2(ull& d, ull a, ull b) {
    asm("fma.rn.f32x2 %0, %1, %2, %0;" : "+l"(d) : "l"(a), "l"(b));
}
__device__ __forceinline__ ull packf2(float x, float y) {
    ull d; asm("mov.b64 %0, {%1, %2};" : "=l"(d) : "f"(x), "f"(y)); return d;
}
__device__ __forceinline__ float2 unpackf2(ull v) {
    float2 r; asm("mov.b64 {%0, %1}, %2;" : "=f"(r.x), "=f"(r.y) : "l"(v)); return r;
}
__device__ __forceinline__ int ld_acq(const int* p) {
    int v; asm volatile("ld.acquire.gpu.global.s32 %0, [%1];" : "=r"(v) : "l"(p) : "memory");
    return v;
}
__device__ __forceinline__ void red_release_add(int* p, int v) {
    asm volatile("red.release.gpu.global.add.s32 [%0], %1;" :: "l"(p), "r"(v) : "memory");
}

// ---------------------------------------------------------------------------
__global__ void bar_init() { g_bar[threadIdx.x] = 0; }

// ---------------------------------------------------------------------------
// Kernel A: XG = seq @ w_ih^T + (b_ih + b_hh). 128x128 tile, BK=8, 256 thr,
// 8x8 per thread, f32x2-packed over m-pairs. (Unchanged; measured ~1.75ms.)
// ---------------------------------------------------------------------------
__global__ __launch_bounds__(256)
void gemm_in(const float* __restrict__ A, const float* __restrict__ W,
             const float* __restrict__ bih, const float* __restrict__ bhh,
             float* __restrict__ C)
{
    __shared__ __align__(16) float As[8][132];
    __shared__ __align__(16) float Bs[8][132];

    const int tid  = threadIdx.x;
    const int tx   = tid & 15;
    const int ty   = tid >> 4;
    const int m0   = blockIdx.y * 128;
    const int n0   = blockIdx.x * 128;
    const int lrow = tid >> 1;
    const int lk4  = (tid & 1) * 4;

    const float* Aptr = A + (size_t)(m0 + lrow) * FIN + lk4;
    const float* Wptr = W + (size_t)(n0 + lrow) * FIN + lk4;

    ull acc2[4][8];
    #pragma unroll
    for (int i = 0; i < 4; i++)
        #pragma unroll
        for (int j = 0; j < 8; j++) acc2[i][j] = 0ULL;

    float4 ra = *(const float4*)(Aptr);
    float4 rb = *(const float4*)(Wptr);

    for (int kb = 0; kb < 64; kb++) {
        As[lk4 + 0][lrow] = ra.x; As[lk4 + 1][lrow] = ra.y;
        As[lk4 + 2][lrow] = ra.z; As[lk4 + 3][lrow] = ra.w;
        Bs[lk4 + 0][lrow] = rb.x; Bs[lk4 + 1][lrow] = rb.y;
        Bs[lk4 + 2][lrow] = rb.z; Bs[lk4 + 3][lrow] = rb.w;
        __syncthreads();

        if (kb < 63) {
            ra = *(const float4*)(Aptr + (kb + 1) * 8);
            rb = *(const float4*)(Wptr + (kb + 1) * 8);
        }

        #pragma unroll
        for (int kk = 0; kk < 8; kk++) {
            ulonglong2 a01 = *(const ulonglong2*)&As[kk][ty * 8];
            ulonglong2 a23 = *(const ulonglong2*)&As[kk][ty * 8 + 4];
            ull av[4] = {a01.x, a01.y, a23.x, a23.y};
            float4 b0 = *(const float4*)&Bs[kk][tx * 8];
            float4 b1 = *(const float4*)&Bs[kk][tx * 8 + 4];
            ull rbk[8];
            rbk[0] = packf2(b0.x, b0.x); rbk[1] = packf2(b0.y, b0.y);
            rbk[2] = packf2(b0.z, b0.z); rbk[3] = packf2(b0.w, b0.w);
            rbk[4] = packf2(b1.x, b1.x); rbk[5] = packf2(b1.y, b1.y);
            rbk[6] = packf2(b1.z, b1.z); rbk[7] = packf2(b1.w, b1.w);
            #pragma unroll
            for (int i2 = 0; i2 < 4; i2++)
                #pragma unroll
                for (int j = 0; j < 8; j++)
                    ffma2(acc2[i2][j], av[i2], rbk[j]);
        }
        __syncthreads();
    }

    float bias[8];
    #pragma unroll
    for (int j = 0; j < 8; j++) {
        int n = n0 + tx * 8 + j;
        bias[j] = bih[n] + bhh[n];
    }
    #pragma unroll
    for (int i2 = 0; i2 < 4; i2++) {
        float r0[8], r1[8];
        #pragma unroll
        for (int j = 0; j < 8; j++) {
            float2 v = unpackf2(acc2[i2][j]);
            r0[j] = v.x + bias[j];
            r1[j] = v.y + bias[j];
        }
        int m = m0 + ty * 8 + 2 * i2;
        float* p0 = C + (size_t)m * G4 + n0 + tx * 8;
        float* p1 = p0 + G4;
        *(float4*)(p0)     = make_float4(r0[0], r0[1], r0[2], r0[3]);
        *(float4*)(p0 + 4) = make_float4(r0[4], r0[5], r0[6], r0[7]);
        *(float4*)(p1)     = make_float4(r1[0], r1[1], r1[2], r1[3]);
        *(float4*)(p1 + 4) = make_float4(r1[4], r1[5], r1[6], r1[7]);
    }
}

// ---------------------------------------------------------------------------
// Kernel B v3b: persistent recurrence, shfl K-half reduce, FIXED smem layout.
//
// Mapping: warp w, lane l: ks=l>>4 (K-half), qq=(l>>2)&3, nn=l&3.
//   u=w*4+qq; batches b0=2u, b0+1; column n = 4*blockIdx.x + nn.
//
// sW layout (16B-aligned + conflict-free):
//   addr(nr, g, k) = nr*SW_NN + g*SW_G + k + (k>=256 ? 4 : 0)
//   SW_G=520 (2080B, 16B-aligned), SW_NN=4*520+8=2088 (8352B, 16B-aligned;
//   2088 mod 32 = 8 -> nn quads {0,8,16,24}); ks adds 260 mod 32 = 4.
//   Per-instruction lane quad = 8*nn + 4*ks -> 8 distinct chunks, 1 phase.
// sH layout: addr(b, k) = b*516 + k + (k>=256 ? 4 : 0)
//   516 floats = 2064B (16B-aligned); b0=2u -> quad 8*qq; ks adds 4.
//   Per-instruction quad = 8*qq + 4*ks -> 8 distinct chunks, 1 phase.
// ---------------------------------------------------------------------------
#define SW_G  520
#define SW_NN 2088
#define SW_FLOATS 8352
#define SH_STRIDE 516
#define SH_FLOATS (64 * SH_STRIDE)      // 33024
#define SMEM_FLOATS (SW_FLOATS + SH_FLOATS)
#define SMEM_BYTES  (SMEM_FLOATS * 4)   // 165504

__global__ __launch_bounds__(256, 1)
void lstm_persist(const float* __restrict__ xg,
                  const float* __restrict__ Whh,
                  float* __restrict__ hout,   // [S][B][H] (hs; doubles as h history)
                  float* __restrict__ cout)   // [S][B][H] (cs)
{
    extern __shared__ __align__(16) float sm[];
    float* sW = sm;                 // staged once, persistent
    float* sH = sm + SW_FLOATS;

    const int tid = threadIdx.x;
    const int w   = tid >> 5;
    const int l   = tid & 31;
    const int ks  = l >> 4;
    const int qq  = (l >> 2) & 3;
    const int nn  = l & 3;
    const int n0  = blockIdx.x * 4;

    // Stage the block's 16 w_hh rows once (row (nr, g), K-half skew +4).
    #pragma unroll
    for (int i = 0; i < 8; i++) {
        int s  = tid + 256 * i;            // 0..2047 float4 units
        int r  = s >> 7;
        int k4 = (s & 127) * 4;
        int g  = r & 3;
        int nr = r >> 2;
        float4 v = *(const float4*)(Whh + (size_t)(g * HH + n0 + nr) * HH + k4);
        float* d = sW + nr * SW_NN + g * SW_G + k4 + (k4 >= 256 ? 4 : 0);
        d[0] = v.x; d[1] = v.y; d[2] = v.z; d[3] = v.w;
    }
    __syncthreads();

    const int u  = w * 4 + qq;        // 0..31
    const int b0 = 2 * u;             // batches b0, b0+1
    const int n  = n0 + nn;

    const float* wb  = sW + nn * SW_NN + ks * 260;         // + g*SW_G + kk
    const float* hbb = sH + b0 * SH_STRIDE + ks * 260;     // + bb*SH_STRIDE + kk

    float c0 = 0.0f, c1 = 0.0f;

    for (int t = 0; t < SQ; t++) {
        if (t > 0) {
            if (tid == 0) { while (ld_acq(&g_bar[t - 1]) < 128) {} }
            __syncthreads();
        }

        // Prefetch this thread's xg[t] early; consumed in the epilogue.
        const float* xgt = xg + (size_t)t * BB * G4 + (size_t)b0 * G4 + n;
        float x00 = xgt[0],         x01 = xgt[512];
        float x02 = xgt[1024],      x03 = xgt[1536];
        float x10 = xgt[G4],        x11 = xgt[G4 + 512];
        float x12 = xgt[G4 + 1024], x13 = xgt[G4 + 1536];

        float s00 = 0.f, s01 = 0.f, s02 = 0.f, s03 = 0.f;
        float s10 = 0.f, s11 = 0.f, s12 = 0.f, s13 = 0.f;

        if (t > 0) {
            // Stage h(t-1): 128KB coalesced, K-half skew +4
            const float* hp = hout + (size_t)(t - 1) * BB * HH;
            #pragma unroll
            for (int i = 0; i < 32; i++) {
                int s  = tid + 256 * i;          // 0..8191 float4 units
                int b  = s >> 7;
                int k4 = (s & 127) * 4;
                float4 v = *(const float4*)(hp + b * HH + k4);
                float* d = sH + b * SH_STRIDE + k4 + (k4 >= 256 ? 4 : 0);
                d[0] = v.x; d[1] = v.y; d[2] = v.z; d[3] = v.w;
            }
            __syncthreads();

            ull a00 = 0, a01 = 0, a02 = 0, a03 = 0;
            ull a10 = 0, a11 = 0, a12 = 0, a13 = 0;

            #pragma unroll 4
            for (int kk = 0; kk < 256; kk += 4) {
                ulonglong2 w0 = *(const ulonglong2*)(wb + kk);
                ulonglong2 w1 = *(const ulonglong2*)(wb + SW_G + kk);
                ulonglong2 w2 = *(const ulonglong2*)(wb + 2 * SW_G + kk);
                ulonglong2 w3 = *(const ulonglong2*)(wb + 3 * SW_G + kk);
                ulonglong2 hA = *(const ulonglong2*)(hbb + kk);
                ulonglong2 hB = *(const ulonglong2*)(hbb + SH_STRIDE + kk);

                ffma2(a00, hA.x, w0.x); ffma2(a00, hA.y, w0.y);
                ffma2(a01, hA.x, w1.x); ffma2(a01, hA.y, w1.y);
                ffma2(a02, hA.x, w2.x); ffma2(a02, hA.y, w2.y);
                ffma2(a03, hA.x, w3.x); ffma2(a03, hA.y, w3.y);
                ffma2(a10, hB.x, w0.x); ffma2(a10, hB.y, w0.y);
                ffma2(a11, hB.x, w1.x); ffma2(a11, hB.y, w1.y);
                ffma2(a12, hB.x, w2.x); ffma2(a12, hB.y, w2.y);
                ffma2(a13, hB.x, w3.x); ffma2(a13, hB.y, w3.y);
            }

            float2 v;
            v = unpackf2(a00); s00 = v.x + v.y;
            v = unpackf2(a01); s01 = v.x + v.y;
            v = unpackf2(a02); s02 = v.x + v.y;
            v = unpackf2(a03); s03 = v.x + v.y;
            v = unpackf2(a10); s10 = v.x + v.y;
            v = unpackf2(a11); s11 = v.x + v.y;
            v = unpackf2(a12); s12 = v.x + v.y;
            v = unpackf2(a13); s13 = v.x + v.y;

            s00 += __shfl_xor_sync(0xffffffffu, s00, 16);
            s01 += __shfl_xor_sync(0xffffffffu, s01, 16);
            s02 += __shfl_xor_sync(0xffffffffu, s02, 16);
            s03 += __shfl_xor_sync(0xffffffffu, s03, 16);
            s10 += __shfl_xor_sync(0xffffffffu, s10, 16);
            s11 += __shfl_xor_sync(0xffffffffu, s11, 16);
            s12 += __shfl_xor_sync(0xffffffffu, s12, 16);
            s13 += __shfl_xor_sync(0xffffffffu, s13, 16);
        }

        // Gate epilogue (order: i, f, g, o). Both ks lanes compute identical
        // state (keeps creg consistent); only ks==0 lanes write.
        float cn0 = sig(x01 + s01) * c0 + sig(x00 + s00) * tanhf(x02 + s02);
        float hn0 = sig(x03 + s03) * tanhf(cn0);
        float cn1 = sig(x11 + s11) * c1 + sig(x10 + s10) * tanhf(x12 + s12);
        float hn1 = sig(x13 + s13) * tanhf(cn1);
        c0 = cn0; c1 = cn1;

        if (ks == 0) {
            float* hO = hout + (size_t)t * BB * HH + (size_t)b0 * HH + n;
            float* cO = cout + (size_t)t * BB * HH + (size_t)b0 * HH + n;
            hO[0]  = hn0; hO[HH] = hn1;
            cO[0]  = cn0; cO[HH] = cn1;
        }

        // Publish step t: bar.sync orders all threads' stores before the
        // release-add (PTX memory-model cumulativity).
        __syncthreads();
        if (tid == 0) red_release_add(&g_bar[t], 1);
    }
}

// ---------------------------------------------------------------------------
// Host
// ---------------------------------------------------------------------------
extern "C" void kernel_launch(void* const* d_in, const int* in_sizes, int n_in,
                              void* d_out, int out_size)
{
    const float* seq = (const float*)d_in[0];
    const float* wih = (const float*)d_in[1];
    const float* whh = (const float*)d_in[2];
    const float* bih = (const float*)d_in[3];
    const float* bhh = (const float*)d_in[4];
    float* out = (float*)d_out;

    float *xg, *cscr;
    cudaGetSymbolAddress((void**)&xg, g_xg);
    cudaGetSymbolAddress((void**)&cscr, g_c);

    const size_t SBH = (size_t)SQ * BB * HH;
    float* cbase = ((size_t)out_size >= 2 * SBH) ? (out + SBH) : cscr;

    bar_init<<<1, SQ>>>();

    dim3 gg(G4 / 128, (SQ * BB) / 128);            // (16, 256)
    gemm_in<<<gg, 256>>>(seq, wih, bih, bhh, xg);

    cudaFuncSetAttribute(lstm_persist, cudaFuncAttributeMaxDynamicSharedMemorySize,
                         SMEM_BYTES);
    lstm_persist<<<128, 256, SMEM_BYTES>>>(xg, whh, out, cbase);
}